// round 5
// baseline (speedup 1.0000x reference)
#include <cuda_runtime.h>
#include <cuda_bf16.h>
#include <math.h>
#include <stdint.h>

// ---------------- problem constants ----------------
#define BB      4
#define LL      4096
#define DMODEL  1024
#define DINNER  2048
#define NHEADS  16
#define DSTATE  64
#define PROJ    4256
#define MROWS   (BB*LL)          // 16384
#define NPAD1   4352             // 34 * 128
#define K3_1    (3*DMODEL)       // 3072
#define K3_2    (3*DINNER)       // 6144

// ---------------- scratch (__device__ globals; no runtime alloc) -------------
__device__ __align__(16) float g_xs   [(size_t)MROWS * DINNER];   // silu(x)
__device__ __align__(16) float g_sz   [(size_t)MROWS * DINNER];   // silu(z)
__device__ __align__(16) float g_tail [(size_t)MROWS * 160];      // B,C,dt,lam raw
__device__ __align__(16) float g_Bc   [(size_t)MROWS * DSTATE];
__device__ __align__(16) float g_Cc   [(size_t)MROWS * DSTATE];
__device__ __align__(16) float g_coef [(size_t)MROWS * NHEADS * 4];
__device__ __align__(16) float g_theta[(size_t)MROWS * 32];
__device__ __align__(16) float g_phi  [(size_t)MROWS * 32];
__device__ __align__(16) float g_csum [(size_t)BB * 64 * 32];
// K-tripled bf16 operands: A'' = [hi, lo, hi], B'' = [hi, hi, lo]
__device__ __align__(16) __nv_bfloat16 g_a3 [(size_t)MROWS * K3_1];
__device__ __align__(16) __nv_bfloat16 g_yz3[(size_t)MROWS * K3_2];
__device__ __align__(16) __nv_bfloat16 g_w31[(size_t)NPAD1 * K3_1];
__device__ __align__(16) __nv_bfloat16 g_w32[(size_t)DMODEL * K3_2];

// ---------------- PTX helpers --------------------------------------------------
__device__ __forceinline__ uint32_t s2u(const void* p)
{
    uint32_t r;
    asm("{ .reg .u64 t; cvta.to.shared.u64 t, %1; cvt.u32.u64 %0, t; }"
        : "=r"(r) : "l"(p));
    return r;
}
__device__ __forceinline__ void cp16(uint32_t d, const void* s)
{
    asm volatile("cp.async.cg.shared.global [%0], [%1], 16;" :: "r"(d), "l"(s));
}
#define CP_COMMIT() asm volatile("cp.async.commit_group;" ::: "memory")
#define CP_WAIT1()  asm volatile("cp.async.wait_group 1;"  ::: "memory")

__device__ __forceinline__ void ldm4(uint32_t* r, uint32_t a)
{
    asm volatile("ldmatrix.sync.aligned.m8n8.x4.shared.b16 {%0,%1,%2,%3}, [%4];"
        : "=r"(r[0]), "=r"(r[1]), "=r"(r[2]), "=r"(r[3]) : "r"(a));
}
__device__ __forceinline__ void mma16816(float* d, const uint32_t* a, const uint32_t* b)
{
    asm volatile("mma.sync.aligned.m16n8k16.row.col.f32.bf16.bf16.f32 "
        "{%0,%1,%2,%3}, {%4,%5,%6,%7}, {%8,%9}, {%0,%1,%2,%3};"
        : "+f"(d[0]), "+f"(d[1]), "+f"(d[2]), "+f"(d[3])
        : "r"(a[0]), "r"(a[1]), "r"(a[2]), "r"(a[3]), "r"(b[0]), "r"(b[1]));
}
__device__ __forceinline__ float silu1(float v)
{
    return v / (1.f + expf(-v));
}
__device__ __forceinline__ uint32_t packbf2(float a, float b)
{
    __nv_bfloat162 t;
    t.x = __float2bfloat16(a);
    t.y = __float2bfloat16(b);
    return *(uint32_t*)&t;
}

// ---------------- layernorm + K3 hi/lo pack + theta -----------------------------
__global__ void __launch_bounds__(256) k_ln_theta(const float* __restrict__ u,
        const float* __restrict__ gscale, const float* __restrict__ gbias,
        const float* __restrict__ tw)
{
    __shared__ float su[1024];
    __shared__ float rsum[8], rsq[8];
    __shared__ float s_mu, s_rs;
    __shared__ float sth[8][32];
    int m = blockIdx.x, tid = threadIdx.x;
    const float* ur = u + (size_t)m * 1024 + tid * 4;
    float4 v = *(const float4*)ur;
    *(float4*)(su + tid * 4) = v;
    float s = v.x + v.y + v.z + v.w;
    float q = v.x*v.x + v.y*v.y + v.z*v.z + v.w*v.w;
    #pragma unroll
    for (int o = 16; o; o >>= 1) {
        s += __shfl_xor_sync(0xffffffffu, s, o);
        q += __shfl_xor_sync(0xffffffffu, q, o);
    }
    int lane = tid & 31, wid = tid >> 5;
    if (lane == 0) { rsum[wid] = s; rsq[wid] = q; }
    __syncthreads();
    if (tid == 0) {
        float S = 0.f, Q = 0.f;
        #pragma unroll
        for (int i = 0; i < 8; i++) { S += rsum[i]; Q += rsq[i]; }
        float mu  = S * (1.f / 1024.f);
        float var = Q * (1.f / 1024.f) - mu * mu;
        s_mu = mu;
        s_rs = rsqrtf(var + 1e-6f);
    }
    __syncthreads();
    float mu = s_mu, rs = s_rs;
    float4 sc = *(const float4*)(gscale + tid * 4);
    float4 bi = *(const float4*)(gbias  + tid * 4);
    float o0 = (v.x - mu) * rs * sc.x + bi.x;
    float o1 = (v.y - mu) * rs * sc.y + bi.y;
    float o2 = (v.z - mu) * rs * sc.z + bi.z;
    float o3 = (v.w - mu) * rs * sc.w + bi.w;
    __nv_bfloat16 h0 = __float2bfloat16(o0), h1 = __float2bfloat16(o1);
    __nv_bfloat16 h2 = __float2bfloat16(o2), h3 = __float2bfloat16(o3);
    __nv_bfloat162 hi01 = {h0, h1}, hi23 = {h2, h3};
    __nv_bfloat162 lo01 = {__float2bfloat16(o0 - __bfloat162float(h0)),
                           __float2bfloat16(o1 - __bfloat162float(h1))};
    __nv_bfloat162 lo23 = {__float2bfloat16(o2 - __bfloat162float(h2)),
                           __float2bfloat16(o3 - __bfloat162float(h3))};
    __nv_bfloat16* row = g_a3 + (size_t)m * K3_1;
    *(__nv_bfloat162*)(row + tid * 4)            = hi01;
    *(__nv_bfloat162*)(row + tid * 4 + 2)        = hi23;
    *(__nv_bfloat162*)(row + 1024 + tid * 4)     = lo01;
    *(__nv_bfloat162*)(row + 1024 + tid * 4 + 2) = lo23;
    *(__nv_bfloat162*)(row + 2048 + tid * 4)     = hi01;
    *(__nv_bfloat162*)(row + 2048 + tid * 4 + 2) = hi23;

    // theta = u_row @ theta_w (32 cols)
    int c = tid & 31, kc = tid >> 5;
    float acc = 0.f;
    const float* twp = tw + kc * 128 * 32 + c;
    const float* sup = su + kc * 128;
    #pragma unroll 8
    for (int kk = 0; kk < 128; ++kk) acc = fmaf(sup[kk], twp[kk * 32], acc);
    sth[kc][c] = acc;
    __syncthreads();
    if (tid < 32) {
        float t2 = 0.f;
        #pragma unroll
        for (int i = 0; i < 8; i++) t2 += sth[i][tid];
        g_theta[(size_t)m * 32 + tid] = t2;
    }
}

// ---------------- weight transpose + K3 split: T[n][3K] = [hi, hi, lo] ---------
__global__ void k_tsplit(const float* __restrict__ W, int K, int N,
                         __nv_bfloat16* __restrict__ T)
{
    __shared__ float t[32][33];
    int nb = blockIdx.x * 32, kb = blockIdx.y * 32;
    int x = threadIdx.x, y = threadIdx.y;   // 32 x 8
    #pragma unroll
    for (int i = 0; i < 32; i += 8) {
        int k = kb + y + i, n = nb + x;
        t[y + i][x] = (n < N) ? W[(size_t)k * N + n] : 0.f;
    }
    __syncthreads();
    #pragma unroll
    for (int i = 0; i < 32; i += 8) {
        int n = nb + y + i, k = kb + x;
        float v = t[x][y + i];
        __nv_bfloat16 h = __float2bfloat16(v);
        __nv_bfloat16 l = __float2bfloat16(v - __bfloat162float(h));
        __nv_bfloat16* row = T + (size_t)n * 3 * K;
        row[k]         = h;
        row[K + k]     = h;
        row[2 * K + k] = l;
    }
}

// ---------------- mma.sync bf16 GEMM --------------------------------------------
// MODE 0: fused proj epilogue (silu(x)->g_xs, silu(z)->g_sz, tail->g_tail)
// MODE 1: C = result + ADD (residual)
#define GSTAGE 32768
#define GSMEM  (3 * GSTAGE)

template<int MODE>
__global__ void __launch_bounds__(256)
k_gemm_mma(const __nv_bfloat16* __restrict__ A, const __nv_bfloat16* __restrict__ B,
           const float* __restrict__ ADD, float* __restrict__ C, int N, int Kp)
{
    extern __shared__ char sm[];
    uint32_t smu = s2u(sm);
    int tid = threadIdx.x, wid = tid >> 5, lane = tid & 31;
    int n0 = blockIdx.x * 128, m0 = blockIdx.y * 128;
    int KT = Kp >> 6;

    auto issue = [&](int kt, int slot) {
        uint32_t st = smu + slot * GSTAGE;
        size_t k0 = (size_t)kt * 64;
        #pragma unroll
        for (int t = 0; t < 4; ++t) {
            int idx = tid + t * 256;
            int rw = idx >> 3, c = idx & 7;
            uint32_t sw = (uint32_t)(rw * 128) + (uint32_t)((c ^ (rw & 7)) << 4);
            cp16(st + sw, A + (size_t)(m0 + rw) * Kp + k0 + c * 8);
        }
        #pragma unroll
        for (int t = 0; t < 4; ++t) {
            int idx = tid + t * 256;
            int rw = idx >> 3, c = idx & 7;
            uint32_t sw = (uint32_t)(rw * 128) + (uint32_t)((c ^ (rw & 7)) << 4);
            cp16(st + 16384 + sw, B + (size_t)(n0 + rw) * Kp + k0 + c * 8);
        }
    };

    issue(0, 0); CP_COMMIT();
    issue(1, 1); CP_COMMIT();

    float d[2][8][4];
    #pragma unroll
    for (int i = 0; i < 2; i++)
        #pragma unroll
        for (int j = 0; j < 8; j++)
            #pragma unroll
            for (int e = 0; e < 4; e++) d[i][j][e] = 0.f;

    int mo = (wid >> 1) * 32, no = (wid & 1) * 64;

    for (int kt = 0; kt < KT; ++kt) {
        CP_WAIT1();
        __syncthreads();
        if (kt + 2 < KT) issue(kt + 2, (kt + 2) % 3);
        CP_COMMIT();

        uint32_t sA = smu + (kt % 3) * GSTAGE;
        uint32_t sB = sA + 16384;
        #pragma unroll
        for (int ks = 0; ks < 4; ++ks) {
            uint32_t a0[4], a1[4], bfr[4][4];
            {
                int r = mo + (lane & 15);
                int c = ks * 2 + (lane >> 4);
                ldm4(a0, sA + (uint32_t)(r * 128) + (uint32_t)((c ^ (r & 7)) << 4));
                r += 16;
                ldm4(a1, sA + (uint32_t)(r * 128) + (uint32_t)((c ^ (r & 7)) << 4));
            }
            #pragma unroll
            for (int nb = 0; nb < 4; ++nb) {
                int r = no + nb * 16 + (lane & 7) + (((lane >> 4) & 1) << 3);
                int c = ks * 2 + ((lane >> 3) & 1);
                ldm4(bfr[nb], sB + (uint32_t)(r * 128) + (uint32_t)((c ^ (r & 7)) << 4));
            }
            #pragma unroll
            for (int ni = 0; ni < 8; ++ni) {
                mma16816(d[0][ni], a0, &bfr[ni >> 1][(ni & 1) * 2]);
                mma16816(d[1][ni], a1, &bfr[ni >> 1][(ni & 1) * 2]);
            }
        }
    }

    // epilogue
    #pragma unroll
    for (int mi = 0; mi < 2; ++mi) {
        int r0 = m0 + mo + mi * 16 + (lane >> 2);
        #pragma unroll
        for (int ni = 0; ni < 8; ++ni) {
            int col = n0 + no + ni * 8 + (lane & 3) * 2;
            #pragma unroll
            for (int half = 0; half < 2; ++half) {
                int row = r0 + half * 8;
                float2 v = {d[mi][ni][half * 2], d[mi][ni][half * 2 + 1]};
                if (MODE == 0) {
                    if (col < 2048) {
                        float2 o = {silu1(v.x), silu1(v.y)};
                        *(float2*)(g_xs + (size_t)row * 2048 + col) = o;
                    } else if (col < 4096) {
                        float2 o = {silu1(v.x), silu1(v.y)};
                        *(float2*)(g_sz + (size_t)row * 2048 + col - 2048) = o;
                    } else if (col < 4256) {
                        *(float2*)(g_tail + (size_t)row * 160 + col - 4096) = v;
                    }
                } else {
                    if (col < N) {
                        float2 a2 = *(const float2*)(ADD + (size_t)row * N + col);
                        v.x += a2.x; v.y += a2.y;
                        *(float2*)(C + (size_t)row * N + col) = v;
                    }
                }
            }
        }
    }
}

// ---------------- per-row prep (tail only): rmsnorm B/C, dt/lam coefs, dphi ----
__global__ void __launch_bounds__(96) k_prep(const float* __restrict__ A_log,
        const float* __restrict__ dt_bias,
        const float* __restrict__ bcB, const float* __restrict__ bcC,
        const float* __restrict__ Bbias, const float* __restrict__ Cbias)
{
    int m = blockIdx.x, tid = threadIdx.x;
    const float* tail = g_tail + (size_t)m * 160;
    __shared__ float s_dts;

    int lane = tid & 31, wid = tid >> 5;
    if (wid == 0) {
        float b0 = tail[lane], b1 = tail[32 + lane];
        float ss = b0 * b0 + b1 * b1;
        #pragma unroll
        for (int o = 16; o; o >>= 1) ss += __shfl_xor_sync(0xffffffffu, ss, o);
        float r = rsqrtf(ss * (1.f / 64.f) + 1e-6f);
        g_Bc[(size_t)m * 64 + lane]      = b0 * r * bcB[lane]      + Bbias[lane];
        g_Bc[(size_t)m * 64 + 32 + lane] = b1 * r * bcB[32 + lane] + Bbias[32 + lane];
    } else if (wid == 1) {
        float b0 = tail[64 + lane], b1 = tail[96 + lane];
        float ss = b0 * b0 + b1 * b1;
        #pragma unroll
        for (int o = 16; o; o >>= 1) ss += __shfl_xor_sync(0xffffffffu, ss, o);
        float r = rsqrtf(ss * (1.f / 64.f) + 1e-6f);
        g_Cc[(size_t)m * 64 + lane]      = b0 * r * bcC[lane]      + Cbias[lane];
        g_Cc[(size_t)m * 64 + 32 + lane] = b1 * r * bcC[32 + lane] + Cbias[32 + lane];
    } else {
        float dt = 0.f;
        if (lane < 16) {
            float x = tail[128 + lane] + dt_bias[lane];
            dt = (x > 20.f) ? x : log1pf(expf(x));
            float lamr = tail[144 + lane];
            float lam = 1.f / (1.f + expf(-lamr));
            float a = expf(-expf(A_log[lane]) * dt);
            size_t o = ((size_t)m * 16 + lane) * 4;
            g_coef[o]     = a;
            g_coef[o + 1] = dt * lam;
            g_coef[o + 2] = dt * (1.f - lam) * a;
            g_coef[o + 3] = 0.f;
        }
        float s = dt;
        #pragma unroll
        for (int o = 16; o; o >>= 1) s += __shfl_xor_sync(0xffffffffu, s, o);
        if (lane == 0) s_dts = s * (1.f / 16.f);
    }
    __syncthreads();
    if (tid < 32)
        g_phi[(size_t)m * 32 + tid] = s_dts * g_theta[(size_t)m * 32 + tid];
}

// ---------------- 3-phase cumsum (phase 3 fused with RoPE) ----------------------
__global__ void k_cs_chunk()
{
    int b = blockIdx.x >> 6, ch = blockIdx.x & 63;
    int c = threadIdx.x;
    size_t base = (((size_t)b * 4096) + (size_t)ch * 64) * 32 + c;
    float acc = 0.f;
    #pragma unroll 8
    for (int l = 0; l < 64; ++l) {
        acc += g_phi[base + (size_t)l * 32];
        g_phi[base + (size_t)l * 32] = acc;
    }
    g_csum[((size_t)(b * 64 + ch)) * 32 + c] = acc;
}
__global__ void k_cs_scan()
{
    int tid = threadIdx.x;
    int b = tid >> 5, c = tid & 31;
    float acc = 0.f;
    for (int ch = 0; ch < 64; ++ch) {
        size_t o = ((size_t)(b * 64 + ch)) * 32 + c;
        float t = g_csum[o];
        g_csum[o] = acc;
        acc += t;
    }
}
__global__ void k_cs_add_rope()
{
    int b = blockIdx.x >> 6, ch = blockIdx.x & 63;
    __shared__ float off[32];
    if (threadIdx.x < 32)
        off[threadIdx.x] = g_csum[((size_t)(b * 64 + ch)) * 32 + threadIdx.x];
    __syncthreads();
    size_t mbase = (size_t)b * 4096 + (size_t)ch * 64;
    for (int e = threadIdx.x; e < 2048; e += 256) {
        int r = e >> 5, c = e & 31;
        size_t m = mbase + r;
        float ph = g_phi[m * 32 + c] + off[c];
        float cc = cosf(ph), ss = sinf(ph);
        size_t o = m * 64 + c;
        float xr = g_Bc[o], xi = g_Bc[o + 32];
        g_Bc[o]      = xr * cc - xi * ss;
        g_Bc[o + 32] = xr * ss + xi * cc;
        xr = g_Cc[o]; xi = g_Cc[o + 32];
        g_Cc[o]      = xr * cc - xi * ss;
        g_Cc[o + 32] = xr * ss + xi * cc;
    }
}

// ---------------- SSD scan + gate + bf16 K3 pack (fused) -------------------------
// grid 256 = (b:4, h:16, pg:4); 256 threads: thread = (pl = tid>>3, nsub = tid&7)
// dynamic smem layout (floats):
//   stage s (s=0,1) at s*6272:  B[32][64] @0, C[32][64] @2048,
//                               x[32][32] @4096, z[32][32] @5120, cf[32][4] @6144
//   ybuf[32][32] @12544
#define SCHUNK 32
#define ST_F   6272
#define SCAN_SMEM ((2 * ST_F + 1024) * 4)   // 54272 bytes

__global__ void __launch_bounds__(256) k_scan(const float* __restrict__ Dv)
{
    extern __shared__ float sf[];
    uint32_t smu = s2u(sf);
    int bx = blockIdx.x;
    int pg = bx & 3, h = (bx >> 2) & 15, b = bx >> 6;
    int tid = threadIdx.x;
    int nsub = tid & 7, pl = tid >> 3;
    size_t mb = (size_t)b * 4096;
    const float* Bg = g_Bc + mb * 64;
    const float* Cg = g_Cc + mb * 64;
    const float* Xg = g_xs + mb * 2048 + h * 128 + pg * 32;
    const float* Zg = g_sz + mb * 2048 + h * 128 + pg * 32;
    const float* Kg = g_coef + (mb * 16 + h) * 4;
    float Dh = Dv[h];
    int jbase = h * 128 + pg * 32;

    auto load_chunk = [&](int c, int slot) {
        int t0 = c * SCHUNK;
        uint32_t sb = smu + slot * ST_F * 4;
        #pragma unroll
        for (int i = 0; i < 2; ++i) {
            int idx = tid + i * 256;
            int t = idx >> 4, seg = idx & 15;
            cp16(sb + (uint32_t)(t * 64 + seg * 4) * 4,
                 Bg + (size_t)(t0 + t) * 64 + seg * 4);
        }
        #pragma unroll
        for (int i = 0; i < 2; ++i) {
            int idx = tid + i * 256;
            int t = idx >> 4, seg = idx & 15;
            cp16(sb + (uint32_t)(2048 + t * 64 + seg * 4) * 4,
                 Cg + (size_t)(t0 + t) * 64 + seg * 4);
        }
        {
            int t = tid >> 3, seg = tid & 7;
            cp16(sb + (uint32_t)(4096 + t * 32 + seg * 4) * 4,
                 Xg + (size_t)(t0 + t) * 2048 + seg * 4);
            cp16(sb + (uint32_t)(5120 + t * 32 + seg * 4) * 4,
                 Zg + (size_t)(t0 + t) * 2048 + seg * 4);
        }
        if (tid < SCHUNK)
            cp16(sb + (uint32_t)(6144 + tid * 4) * 4,
                 Kg + (size_t)(t0 + tid) * 64);
    };

    float hs[8], Bprev[8];
    #pragma unroll
    for (int i = 0; i < 8; i++) { hs[i] = 0.f; Bprev[i] = 0.f; }
    float xprev = 0.f;
    float* ybuf = sf + 2 * ST_F;

    load_chunk(0, 0); CP_COMMIT();
    load_chunk(1, 1); CP_COMMIT();

    const int NCHUNK = LL / SCHUNK;   // 128
    for (int c = 0; c < NCHUNK; ++c) {
        int slot = c & 1;
        const float* st = sf + slot * ST_F;
        CP_WAIT1();
        __syncthreads();
        #pragma unroll 4
        for (int t = 0; t < SCHUNK; ++t) {
            float4 b0 = *(const float4*)(st + t * 64 + nsub * 8);
            float4 b1 = *(const float4*)(st + t * 64 + nsub * 8 + 4);
            float4 c0 = *(const float4*)(st + 2048 + t * 64 + nsub * 8);
            float4 c1 = *(const float4*)(st + 2048 + t * 64 + nsub * 8 + 4);
            float4 cf = *(const float4*)(st + 6144 + t * 4);
            float xc = st[4096 + t * 32 + pl];
            float ca  = cf.x;
            float c1x = cf.y * xc;
            float c2x = cf.z * xprev;
            float Bn[8] = {b0.x, b0.y, b0.z, b0.w, b1.x, b1.y, b1.z, b1.w};
            float Cn[8] = {c0.x, c0.y, c0.z, c0.w, c1.x, c1.y, c1.z, c1.w};
            float acc = 0.f;
            #pragma unroll
            for (int i = 0; i < 8; i++) {
                float bx_ = fmaf(c1x, Bn[i], c2x * Bprev[i]);
                hs[i] = fmaf(ca, hs[i], bx_);
                acc = fmaf(hs[i], Cn[i], acc);
                Bprev[i] = Bn[i];
            }
            xprev = xc;
            acc += __shfl_xor_sync(0xffffffffu, acc, 1);
            acc += __shfl_xor_sync(0xffffffffu, acc, 2);
            acc += __shfl_xor_sync(0xffffffffu, acc, 4);
            if (nsub == 0) {
                float zc = st[5120 + t * 32 + pl];
                ybuf[t * 32 + pl] = fmaf(Dh, xc, acc) * zc;
            }
        }
        __syncthreads();   // ybuf complete; all stage reads done
        // pack ybuf -> g_yz3 (hi @ j, lo @ 2048+j, hi @ 4096+j)
        {
            int e0 = tid * 4;
            int t = e0 >> 5, p0 = e0 & 31;
            float4 y4 = *(const float4*)(ybuf + t * 32 + p0);
            uint32_t h01 = packbf2(y4.x, y4.y);
            uint32_t h23 = packbf2(y4.z, y4.w);
            __nv_bfloat162 hv01 = *(__nv_bfloat162*)&h01;
            __nv_bfloat162 hv23 = *(__nv_bfloat162*)&h23;
            uint32_t l01 = packbf2(y4.x - __bfloat162float(hv01.x),
                                   y4.y - __bfloat162float(hv01.y));
            uint32_t l23 = packbf2(y4.z - __bfloat162float(hv23.x),
                                   y4.w - __bfloat162float(hv23.y));
            size_t row = mb + (size_t)c * SCHUNK + t;
            __nv_bfloat16* rp = g_yz3 + row * K3_2 + jbase + p0;
            uint2 H = {h01, h23}, L = {l01, l23};
            *(uint2*)rp          = H;
            *(uint2*)(rp + 2048) = L;
            *(uint2*)(rp + 4096) = H;
        }
        if (c + 2 < NCHUNK) load_chunk(c + 2, slot);
        CP_COMMIT();
    }
}

// ---------------- host launcher --------------------------------------------------
template<typename T>
static T* sym_addr(const void* s)
{
    void* p = nullptr;
    cudaGetSymbolAddress(&p, s);
    return (T*)p;
}

extern "C" void kernel_launch(void* const* d_in, const int* in_sizes, int n_in,
                              void* d_out, int out_size)
{
    const float* u          = (const float*)d_in[0];
    const float* norm_scale = (const float*)d_in[1];
    const float* norm_bias  = (const float*)d_in[2];
    const float* in_proj_w  = (const float*)d_in[3];
    const float* A_log      = (const float*)d_in[4];
    const float* dt_bias    = (const float*)d_in[5];
    const float* bcB_scale  = (const float*)d_in[6];
    const float* bcC_scale  = (const float*)d_in[7];
    const float* B_bias     = (const float*)d_in[8];
    const float* C_bias     = (const float*)d_in[9];
    const float* theta_w    = (const float*)d_in[10];
    const float* Dv         = (const float*)d_in[11];
    const float* out_proj_w = (const float*)d_in[12];
    float* out = (float*)d_out;

    __nv_bfloat16* p_a3  = sym_addr<__nv_bfloat16>(g_a3);
    __nv_bfloat16* p_yz3 = sym_addr<__nv_bfloat16>(g_yz3);
    __nv_bfloat16* p_w31 = sym_addr<__nv_bfloat16>(g_w31);
    __nv_bfloat16* p_w32 = sym_addr<__nv_bfloat16>(g_w32);

    static bool attr_done = false;
    if (!attr_done) {
        cudaFuncSetAttribute(k_gemm_mma<0>,
            cudaFuncAttributeMaxDynamicSharedMemorySize, GSMEM);
        cudaFuncSetAttribute(k_gemm_mma<1>,
            cudaFuncAttributeMaxDynamicSharedMemorySize, GSMEM);
        cudaFuncSetAttribute(k_scan,
            cudaFuncAttributeMaxDynamicSharedMemorySize, SCAN_SMEM);
        attr_done = true;
    }

    // 1. layernorm + hi/lo pack + theta
    k_ln_theta<<<MROWS, 256>>>(u, norm_scale, norm_bias, theta_w);
    // 2. weight transpose + hi/lo pack
    k_tsplit<<<dim3(NPAD1 / 32, DMODEL / 32), dim3(32, 8)>>>(
        in_proj_w, DMODEL, PROJ, p_w31);
    k_tsplit<<<dim3(DMODEL / 32, DINNER / 32), dim3(32, 8)>>>(
        out_proj_w, DINNER, DMODEL, p_w32);
    // 3. proj GEMM (fused epilogue: silu(x), silu(z), tail)
    k_gemm_mma<0><<<dim3(NPAD1 / 128, MROWS / 128), 256, GSMEM>>>(
        p_a3, p_w31, nullptr, nullptr, PROJ, K3_1);
    // 4. tail prep
    k_prep<<<MROWS, 96>>>(A_log, dt_bias, bcB_scale, bcC_scale, B_bias, C_bias);
    // 5. cumsum(phi) + fused RoPE
    k_cs_chunk<<<BB * 64, 32>>>();
    k_cs_scan<<<1, 128>>>();
    k_cs_add_rope<<<BB * 64, 256>>>();
    // 6. SSD scan + gate + pack (fused)
    k_scan<<<256, 256, SCAN_SMEM>>>(Dv);
    // 7. out = yz @ out_proj_w + u
    k_gemm_mma<1><<<dim3(DMODEL / 128, MROWS / 128), 256, GSMEM>>>(
        p_yz3, p_w32, u, out, DMODEL, K3_2);
}

// round 6
// speedup vs baseline: 1.0090x; 1.0090x over previous
#include <cuda_runtime.h>
#include <cuda_bf16.h>
#include <math.h>
#include <stdint.h>

// ---------------- problem constants ----------------
#define BB      4
#define LL      4096
#define DMODEL  1024
#define DINNER  2048
#define NHEADS  16
#define DSTATE  64
#define PROJ    4256
#define MROWS   (BB*LL)          // 16384
#define NPAD1   4352             // 34 * 128
#define K3_1    (3*DMODEL)       // 3072
#define K3_2    (3*DINNER)       // 6144

typedef unsigned long long u64;

// ---------------- scratch (__device__ globals; no runtime alloc) -------------
__device__ __align__(16) float g_xs   [(size_t)MROWS * DINNER];   // silu(x)
__device__ __align__(16) float g_sz   [(size_t)MROWS * DINNER];   // silu(z)
__device__ __align__(16) float g_tail [(size_t)MROWS * 160];      // B,C,dt,lam raw
__device__ __align__(16) float g_Bc   [(size_t)MROWS * DSTATE];
__device__ __align__(16) float g_Cc   [(size_t)MROWS * DSTATE];
__device__ __align__(16) float g_coef [(size_t)MROWS * NHEADS * 4];
__device__ __align__(16) float g_theta[(size_t)MROWS * 32];
__device__ __align__(16) float g_phi  [(size_t)MROWS * 32];
__device__ __align__(16) float g_csum [(size_t)BB * 64 * 32];
// K-tripled bf16 operands: A'' = [hi, lo, hi], B'' = [hi, hi, lo]
__device__ __align__(16) __nv_bfloat16 g_a3 [(size_t)MROWS * K3_1];
__device__ __align__(16) __nv_bfloat16 g_yz3[(size_t)MROWS * K3_2];
__device__ __align__(16) __nv_bfloat16 g_w31[(size_t)NPAD1 * K3_1];
__device__ __align__(16) __nv_bfloat16 g_w32[(size_t)DMODEL * K3_2];

// ---------------- PTX helpers --------------------------------------------------
__device__ __forceinline__ uint32_t s2u(const void* p)
{
    uint32_t r;
    asm("{ .reg .u64 t; cvta.to.shared.u64 t, %1; cvt.u32.u64 %0, t; }"
        : "=r"(r) : "l"(p));
    return r;
}
__device__ __forceinline__ void cp16(uint32_t d, const void* s)
{
    asm volatile("cp.async.cg.shared.global [%0], [%1], 16;" :: "r"(d), "l"(s));
}
#define CP_COMMIT() asm volatile("cp.async.commit_group;" ::: "memory")
#define CP_WAIT1()  asm volatile("cp.async.wait_group 1;"  ::: "memory")

__device__ __forceinline__ void ldm4(uint32_t* r, uint32_t a)
{
    asm volatile("ldmatrix.sync.aligned.m8n8.x4.shared.b16 {%0,%1,%2,%3}, [%4];"
        : "=r"(r[0]), "=r"(r[1]), "=r"(r[2]), "=r"(r[3]) : "r"(a));
}
__device__ __forceinline__ void mma16816(float* d, const uint32_t* a, const uint32_t* b)
{
    asm volatile("mma.sync.aligned.m16n8k16.row.col.f32.bf16.bf16.f32 "
        "{%0,%1,%2,%3}, {%4,%5,%6,%7}, {%8,%9}, {%0,%1,%2,%3};"
        : "+f"(d[0]), "+f"(d[1]), "+f"(d[2]), "+f"(d[3])
        : "r"(a[0]), "r"(a[1]), "r"(a[2]), "r"(a[3]), "r"(b[0]), "r"(b[1]));
}
__device__ __forceinline__ float silu1(float v)
{
    return v / (1.f + expf(-v));
}
__device__ __forceinline__ uint32_t packbf2(float a, float b)
{
    __nv_bfloat162 t;
    t.x = __float2bfloat16(a);
    t.y = __float2bfloat16(b);
    return *(uint32_t*)&t;
}
// ---- packed f32x2 (Blackwell sm_100+) ----
__device__ __forceinline__ u64 pk2(float x, float y)
{
    u64 r;
    asm("mov.b64 %0, {%1, %2};" : "=l"(r) : "f"(x), "f"(y));
    return r;
}
__device__ __forceinline__ void upk2(float& x, float& y, u64 v)
{
    asm("mov.b64 {%0, %1}, %2;" : "=f"(x), "=f"(y) : "l"(v));
}
__device__ __forceinline__ u64 fma2_(u64 a, u64 b, u64 c)
{
    u64 d;
    asm("fma.rn.f32x2 %0, %1, %2, %3;" : "=l"(d) : "l"(a), "l"(b), "l"(c));
    return d;
}
__device__ __forceinline__ u64 mul2_(u64 a, u64 b)
{
    u64 d;
    asm("mul.rn.f32x2 %0, %1, %2;" : "=l"(d) : "l"(a), "l"(b));
    return d;
}

// ---------------- layernorm + K3 hi/lo pack + theta -----------------------------
__global__ void __launch_bounds__(256) k_ln_theta(const float* __restrict__ u,
        const float* __restrict__ gscale, const float* __restrict__ gbias,
        const float* __restrict__ tw)
{
    __shared__ float su[1024];
    __shared__ float rsum[8], rsq[8];
    __shared__ float s_mu, s_rs;
    __shared__ float sth[8][32];
    int m = blockIdx.x, tid = threadIdx.x;
    const float* ur = u + (size_t)m * 1024 + tid * 4;
    float4 v = *(const float4*)ur;
    *(float4*)(su + tid * 4) = v;
    float s = v.x + v.y + v.z + v.w;
    float q = v.x*v.x + v.y*v.y + v.z*v.z + v.w*v.w;
    #pragma unroll
    for (int o = 16; o; o >>= 1) {
        s += __shfl_xor_sync(0xffffffffu, s, o);
        q += __shfl_xor_sync(0xffffffffu, q, o);
    }
    int lane = tid & 31, wid = tid >> 5;
    if (lane == 0) { rsum[wid] = s; rsq[wid] = q; }
    __syncthreads();
    if (tid == 0) {
        float S = 0.f, Q = 0.f;
        #pragma unroll
        for (int i = 0; i < 8; i++) { S += rsum[i]; Q += rsq[i]; }
        float mu  = S * (1.f / 1024.f);
        float var = Q * (1.f / 1024.f) - mu * mu;
        s_mu = mu;
        s_rs = rsqrtf(var + 1e-6f);
    }
    __syncthreads();
    float mu = s_mu, rs = s_rs;
    float4 sc = *(const float4*)(gscale + tid * 4);
    float4 bi = *(const float4*)(gbias  + tid * 4);
    float o0 = (v.x - mu) * rs * sc.x + bi.x;
    float o1 = (v.y - mu) * rs * sc.y + bi.y;
    float o2 = (v.z - mu) * rs * sc.z + bi.z;
    float o3 = (v.w - mu) * rs * sc.w + bi.w;
    __nv_bfloat16 h0 = __float2bfloat16(o0), h1 = __float2bfloat16(o1);
    __nv_bfloat16 h2 = __float2bfloat16(o2), h3 = __float2bfloat16(o3);
    __nv_bfloat162 hi01 = {h0, h1}, hi23 = {h2, h3};
    __nv_bfloat162 lo01 = {__float2bfloat16(o0 - __bfloat162float(h0)),
                           __float2bfloat16(o1 - __bfloat162float(h1))};
    __nv_bfloat162 lo23 = {__float2bfloat16(o2 - __bfloat162float(h2)),
                           __float2bfloat16(o3 - __bfloat162float(h3))};
    __nv_bfloat16* row = g_a3 + (size_t)m * K3_1;
    *(__nv_bfloat162*)(row + tid * 4)            = hi01;
    *(__nv_bfloat162*)(row + tid * 4 + 2)        = hi23;
    *(__nv_bfloat162*)(row + 1024 + tid * 4)     = lo01;
    *(__nv_bfloat162*)(row + 1024 + tid * 4 + 2) = lo23;
    *(__nv_bfloat162*)(row + 2048 + tid * 4)     = hi01;
    *(__nv_bfloat162*)(row + 2048 + tid * 4 + 2) = hi23;

    // theta = u_row @ theta_w (32 cols)
    int c = tid & 31, kc = tid >> 5;
    float acc = 0.f;
    const float* twp = tw + kc * 128 * 32 + c;
    const float* sup = su + kc * 128;
    #pragma unroll 8
    for (int kk = 0; kk < 128; ++kk) acc = fmaf(sup[kk], twp[kk * 32], acc);
    sth[kc][c] = acc;
    __syncthreads();
    if (tid < 32) {
        float t2 = 0.f;
        #pragma unroll
        for (int i = 0; i < 8; i++) t2 += sth[i][tid];
        g_theta[(size_t)m * 32 + tid] = t2;
    }
}

// ---------------- weight transpose + K3 split: T[n][3K] = [hi, hi, lo] ---------
__global__ void k_tsplit(const float* __restrict__ W, int K, int N,
                         __nv_bfloat16* __restrict__ T)
{
    __shared__ float t[32][33];
    int nb = blockIdx.x * 32, kb = blockIdx.y * 32;
    int x = threadIdx.x, y = threadIdx.y;   // 32 x 8
    #pragma unroll
    for (int i = 0; i < 32; i += 8) {
        int k = kb + y + i, n = nb + x;
        t[y + i][x] = (n < N) ? W[(size_t)k * N + n] : 0.f;
    }
    __syncthreads();
    #pragma unroll
    for (int i = 0; i < 32; i += 8) {
        int n = nb + y + i, k = kb + x;
        float v = t[x][y + i];
        __nv_bfloat16 h = __float2bfloat16(v);
        __nv_bfloat16 l = __float2bfloat16(v - __bfloat162float(h));
        __nv_bfloat16* row = T + (size_t)n * 3 * K;
        row[k]         = h;
        row[K + k]     = h;
        row[2 * K + k] = l;
    }
}

// ---------------- mma.sync bf16 GEMM --------------------------------------------
// MODE 0: fused proj epilogue (silu(x)->g_xs, silu(z)->g_sz, tail->g_tail)
// MODE 1: C = result + ADD (residual)
#define GSTAGE 32768
#define GSMEM  (3 * GSTAGE)

template<int MODE>
__global__ void __launch_bounds__(256)
k_gemm_mma(const __nv_bfloat16* __restrict__ A, const __nv_bfloat16* __restrict__ B,
           const float* __restrict__ ADD, float* __restrict__ C, int N, int Kp)
{
    extern __shared__ char sm[];
    uint32_t smu = s2u(sm);
    int tid = threadIdx.x, wid = tid >> 5, lane = tid & 31;
    int n0 = blockIdx.x * 128, m0 = blockIdx.y * 128;
    int KT = Kp >> 6;

    auto issue = [&](int kt, int slot) {
        uint32_t st = smu + slot * GSTAGE;
        size_t k0 = (size_t)kt * 64;
        #pragma unroll
        for (int t = 0; t < 4; ++t) {
            int idx = tid + t * 256;
            int rw = idx >> 3, c = idx & 7;
            uint32_t sw = (uint32_t)(rw * 128) + (uint32_t)((c ^ (rw & 7)) << 4);
            cp16(st + sw, A + (size_t)(m0 + rw) * Kp + k0 + c * 8);
        }
        #pragma unroll
        for (int t = 0; t < 4; ++t) {
            int idx = tid + t * 256;
            int rw = idx >> 3, c = idx & 7;
            uint32_t sw = (uint32_t)(rw * 128) + (uint32_t)((c ^ (rw & 7)) << 4);
            cp16(st + 16384 + sw, B + (size_t)(n0 + rw) * Kp + k0 + c * 8);
        }
    };

    issue(0, 0); CP_COMMIT();
    issue(1, 1); CP_COMMIT();

    float d[2][8][4];
    #pragma unroll
    for (int i = 0; i < 2; i++)
        #pragma unroll
        for (int j = 0; j < 8; j++)
            #pragma unroll
            for (int e = 0; e < 4; e++) d[i][j][e] = 0.f;

    int mo = (wid >> 1) * 32, no = (wid & 1) * 64;

    for (int kt = 0; kt < KT; ++kt) {
        CP_WAIT1();
        __syncthreads();
        if (kt + 2 < KT) issue(kt + 2, (kt + 2) % 3);
        CP_COMMIT();

        uint32_t sA = smu + (kt % 3) * GSTAGE;
        uint32_t sB = sA + 16384;
        #pragma unroll
        for (int ks = 0; ks < 4; ++ks) {
            uint32_t a0[4], a1[4], bfr[4][4];
            {
                int r = mo + (lane & 15);
                int c = ks * 2 + (lane >> 4);
                ldm4(a0, sA + (uint32_t)(r * 128) + (uint32_t)((c ^ (r & 7)) << 4));
                r += 16;
                ldm4(a1, sA + (uint32_t)(r * 128) + (uint32_t)((c ^ (r & 7)) << 4));
            }
            #pragma unroll
            for (int nb = 0; nb < 4; ++nb) {
                int r = no + nb * 16 + (lane & 7) + (((lane >> 4) & 1) << 3);
                int c = ks * 2 + ((lane >> 3) & 1);
                ldm4(bfr[nb], sB + (uint32_t)(r * 128) + (uint32_t)((c ^ (r & 7)) << 4));
            }
            #pragma unroll
            for (int ni = 0; ni < 8; ++ni) {
                mma16816(d[0][ni], a0, &bfr[ni >> 1][(ni & 1) * 2]);
                mma16816(d[1][ni], a1, &bfr[ni >> 1][(ni & 1) * 2]);
            }
        }
    }

    // epilogue
    #pragma unroll
    for (int mi = 0; mi < 2; ++mi) {
        int r0 = m0 + mo + mi * 16 + (lane >> 2);
        #pragma unroll
        for (int ni = 0; ni < 8; ++ni) {
            int col = n0 + no + ni * 8 + (lane & 3) * 2;
            #pragma unroll
            for (int half = 0; half < 2; ++half) {
                int row = r0 + half * 8;
                float2 v = {d[mi][ni][half * 2], d[mi][ni][half * 2 + 1]};
                if (MODE == 0) {
                    if (col < 2048) {
                        float2 o = {silu1(v.x), silu1(v.y)};
                        *(float2*)(g_xs + (size_t)row * 2048 + col) = o;
                    } else if (col < 4096) {
                        float2 o = {silu1(v.x), silu1(v.y)};
                        *(float2*)(g_sz + (size_t)row * 2048 + col - 2048) = o;
                    } else if (col < 4256) {
                        *(float2*)(g_tail + (size_t)row * 160 + col - 4096) = v;
                    }
                } else {
                    if (col < N) {
                        float2 a2 = *(const float2*)(ADD + (size_t)row * N + col);
                        v.x += a2.x; v.y += a2.y;
                        *(float2*)(C + (size_t)row * N + col) = v;
                    }
                }
            }
        }
    }
}

// ---------------- per-row prep (tail only): rmsnorm B/C, dt/lam coefs, dphi ----
__global__ void __launch_bounds__(96) k_prep(const float* __restrict__ A_log,
        const float* __restrict__ dt_bias,
        const float* __restrict__ bcB, const float* __restrict__ bcC,
        const float* __restrict__ Bbias, const float* __restrict__ Cbias)
{
    int m = blockIdx.x, tid = threadIdx.x;
    const float* tail = g_tail + (size_t)m * 160;
    __shared__ float s_dts;

    int lane = tid & 31, wid = tid >> 5;
    if (wid == 0) {
        float b0 = tail[lane], b1 = tail[32 + lane];
        float ss = b0 * b0 + b1 * b1;
        #pragma unroll
        for (int o = 16; o; o >>= 1) ss += __shfl_xor_sync(0xffffffffu, ss, o);
        float r = rsqrtf(ss * (1.f / 64.f) + 1e-6f);
        g_Bc[(size_t)m * 64 + lane]      = b0 * r * bcB[lane]      + Bbias[lane];
        g_Bc[(size_t)m * 64 + 32 + lane] = b1 * r * bcB[32 + lane] + Bbias[32 + lane];
    } else if (wid == 1) {
        float b0 = tail[64 + lane], b1 = tail[96 + lane];
        float ss = b0 * b0 + b1 * b1;
        #pragma unroll
        for (int o = 16; o; o >>= 1) ss += __shfl_xor_sync(0xffffffffu, ss, o);
        float r = rsqrtf(ss * (1.f / 64.f) + 1e-6f);
        g_Cc[(size_t)m * 64 + lane]      = b0 * r * bcC[lane]      + Cbias[lane];
        g_Cc[(size_t)m * 64 + 32 + lane] = b1 * r * bcC[32 + lane] + Cbias[32 + lane];
    } else {
        float dt = 0.f;
        if (lane < 16) {
            float x = tail[128 + lane] + dt_bias[lane];
            dt = (x > 20.f) ? x : log1pf(expf(x));
            float lamr = tail[144 + lane];
            float lam = 1.f / (1.f + expf(-lamr));
            float a = expf(-expf(A_log[lane]) * dt);
            size_t o = ((size_t)m * 16 + lane) * 4;
            g_coef[o]     = a;
            g_coef[o + 1] = dt * lam;
            g_coef[o + 2] = dt * (1.f - lam) * a;
            g_coef[o + 3] = 0.f;
        }
        float s = dt;
        #pragma unroll
        for (int o = 16; o; o >>= 1) s += __shfl_xor_sync(0xffffffffu, s, o);
        if (lane == 0) s_dts = s * (1.f / 16.f);
    }
    __syncthreads();
    if (tid < 32)
        g_phi[(size_t)m * 32 + tid] = s_dts * g_theta[(size_t)m * 32 + tid];
}

// ---------------- 3-phase cumsum (phase 3 fused with RoPE) ----------------------
__global__ void k_cs_chunk()
{
    int b = blockIdx.x >> 6, ch = blockIdx.x & 63;
    int c = threadIdx.x;
    size_t base = (((size_t)b * 4096) + (size_t)ch * 64) * 32 + c;
    float acc = 0.f;
    #pragma unroll 8
    for (int l = 0; l < 64; ++l) {
        acc += g_phi[base + (size_t)l * 32];
        g_phi[base + (size_t)l * 32] = acc;
    }
    g_csum[((size_t)(b * 64 + ch)) * 32 + c] = acc;
}
__global__ void k_cs_scan()
{
    int tid = threadIdx.x;
    int b = tid >> 5, c = tid & 31;
    float acc = 0.f;
    for (int ch = 0; ch < 64; ++ch) {
        size_t o = ((size_t)(b * 64 + ch)) * 32 + c;
        float t = g_csum[o];
        g_csum[o] = acc;
        acc += t;
    }
}
__global__ void k_cs_add_rope()
{
    int b = blockIdx.x >> 6, ch = blockIdx.x & 63;
    __shared__ float off[32];
    if (threadIdx.x < 32)
        off[threadIdx.x] = g_csum[((size_t)(b * 64 + ch)) * 32 + threadIdx.x];
    __syncthreads();
    size_t mbase = (size_t)b * 4096 + (size_t)ch * 64;
    for (int e = threadIdx.x; e < 2048; e += 256) {
        int r = e >> 5, c = e & 31;
        size_t m = mbase + r;
        float ph = g_phi[m * 32 + c] + off[c];
        float cc = cosf(ph), ss = sinf(ph);
        size_t o = m * 64 + c;
        float xr = g_Bc[o], xi = g_Bc[o + 32];
        g_Bc[o]      = xr * cc - xi * ss;
        g_Bc[o + 32] = xr * ss + xi * cc;
        xr = g_Cc[o]; xi = g_Cc[o + 32];
        g_Cc[o]      = xr * cc - xi * ss;
        g_Cc[o + 32] = xr * ss + xi * cc;
    }
}

// ---------------- SSD scan + gate + bf16 K3 pack (fused, f32x2 core) ------------
// grid 256 = (b:4, h:16, pg:4); 256 threads: thread = (pl = tid>>3, nsub = tid&7)
#define SCHUNK 32
#define ST_F   6272
#define SCAN_SMEM ((2 * ST_F + 1024) * 4)   // 54272 bytes

__global__ void __launch_bounds__(256) k_scan(const float* __restrict__ Dv)
{
    extern __shared__ float sf[];
    uint32_t smu = s2u(sf);
    int bx = blockIdx.x;
    int pg = bx & 3, h = (bx >> 2) & 15, b = bx >> 6;
    int tid = threadIdx.x;
    int nsub = tid & 7, pl = tid >> 3;
    size_t mb = (size_t)b * 4096;
    const float* Bg = g_Bc + mb * 64;
    const float* Cg = g_Cc + mb * 64;
    const float* Xg = g_xs + mb * 2048 + h * 128 + pg * 32;
    const float* Zg = g_sz + mb * 2048 + h * 128 + pg * 32;
    const float* Kg = g_coef + (mb * 16 + h) * 4;
    float Dh = Dv[h];
    int jbase = h * 128 + pg * 32;

    auto load_chunk = [&](int c, int slot) {
        int t0 = c * SCHUNK;
        uint32_t sb = smu + slot * ST_F * 4;
        #pragma unroll
        for (int i = 0; i < 2; ++i) {
            int idx = tid + i * 256;
            int t = idx >> 4, seg = idx & 15;
            cp16(sb + (uint32_t)(t * 64 + seg * 4) * 4,
                 Bg + (size_t)(t0 + t) * 64 + seg * 4);
        }
        #pragma unroll
        for (int i = 0; i < 2; ++i) {
            int idx = tid + i * 256;
            int t = idx >> 4, seg = idx & 15;
            cp16(sb + (uint32_t)(2048 + t * 64 + seg * 4) * 4,
                 Cg + (size_t)(t0 + t) * 64 + seg * 4);
        }
        {
            int t = tid >> 3, seg = tid & 7;
            cp16(sb + (uint32_t)(4096 + t * 32 + seg * 4) * 4,
                 Xg + (size_t)(t0 + t) * 2048 + seg * 4);
            cp16(sb + (uint32_t)(5120 + t * 32 + seg * 4) * 4,
                 Zg + (size_t)(t0 + t) * 2048 + seg * 4);
        }
        if (tid < SCHUNK)
            cp16(sb + (uint32_t)(6144 + tid * 4) * 4,
                 Kg + (size_t)(t0 + tid) * 64);
    };

    u64 hs2[4], Bp2[4];
    #pragma unroll
    for (int i = 0; i < 4; i++) { hs2[i] = 0ull; Bp2[i] = 0ull; }
    float xprev = 0.f;
    float* ybuf = sf + 2 * ST_F;

    load_chunk(0, 0); CP_COMMIT();
    load_chunk(1, 1); CP_COMMIT();

    const int NCHUNK = LL / SCHUNK;   // 128
    for (int c = 0; c < NCHUNK; ++c) {
        int slot = c & 1;
        const float* st = sf + slot * ST_F;
        CP_WAIT1();
        __syncthreads();
        #pragma unroll 4
        for (int t = 0; t < SCHUNK; ++t) {
            ulonglong2 B01 = *(const ulonglong2*)(st + t * 64 + nsub * 8);
            ulonglong2 B23 = *(const ulonglong2*)(st + t * 64 + nsub * 8 + 4);
            ulonglong2 C01 = *(const ulonglong2*)(st + 2048 + t * 64 + nsub * 8);
            ulonglong2 C23 = *(const ulonglong2*)(st + 2048 + t * 64 + nsub * 8 + 4);
            float4 cf = *(const float4*)(st + 6144 + t * 4);
            float xc = st[4096 + t * 32 + pl];
            float c1x = cf.y * xc;
            float c2x = cf.z * xprev;
            u64 ca2  = pk2(cf.x, cf.x);
            u64 c1x2 = pk2(c1x, c1x);
            u64 c2x2 = pk2(c2x, c2x);
            u64 Bn[4] = {B01.x, B01.y, B23.x, B23.y};
            u64 Cn[4] = {C01.x, C01.y, C23.x, C23.y};
            u64 acc2 = 0ull;
            #pragma unroll
            for (int i = 0; i < 4; i++) {
                u64 bx_ = fma2_(c1x2, Bn[i], mul2_(c2x2, Bp2[i]));
                hs2[i] = fma2_(ca2, hs2[i], bx_);
                acc2 = fma2_(hs2[i], Cn[i], acc2);
                Bp2[i] = Bn[i];
            }
            float alo, ahi;
            upk2(alo, ahi, acc2);
            float acc = alo + ahi;
            xprev = xc;
            acc += __shfl_xor_sync(0xffffffffu, acc, 1);
            acc += __shfl_xor_sync(0xffffffffu, acc, 2);
            acc += __shfl_xor_sync(0xffffffffu, acc, 4);
            if (nsub == 0) {
                float zc = st[5120 + t * 32 + pl];
                ybuf[t * 32 + pl] = fmaf(Dh, xc, acc) * zc;
            }
        }
        __syncthreads();   // ybuf complete; all stage reads done
        // pack ybuf -> g_yz3 (hi @ j, lo @ 2048+j, hi @ 4096+j)
        {
            int e0 = tid * 4;
            int t = e0 >> 5, p0 = e0 & 31;
            float4 y4 = *(const float4*)(ybuf + t * 32 + p0);
            uint32_t h01 = packbf2(y4.x, y4.y);
            uint32_t h23 = packbf2(y4.z, y4.w);
            __nv_bfloat162 hv01 = *(__nv_bfloat162*)&h01;
            __nv_bfloat162 hv23 = *(__nv_bfloat162*)&h23;
            uint32_t l01 = packbf2(y4.x - __bfloat162float(hv01.x),
                                   y4.y - __bfloat162float(hv01.y));
            uint32_t l23 = packbf2(y4.z - __bfloat162float(hv23.x),
                                   y4.w - __bfloat162float(hv23.y));
            size_t row = mb + (size_t)c * SCHUNK + t;
            __nv_bfloat16* rp = g_yz3 + row * K3_2 + jbase + p0;
            uint2 H = {h01, h23}, L = {l01, l23};
            *(uint2*)rp          = H;
            *(uint2*)(rp + 2048) = L;
            *(uint2*)(rp + 4096) = H;
        }
        if (c + 2 < NCHUNK) load_chunk(c + 2, slot);
        CP_COMMIT();
    }
}

// ---------------- host launcher --------------------------------------------------
template<typename T>
static T* sym_addr(const void* s)
{
    void* p = nullptr;
    cudaGetSymbolAddress(&p, s);
    return (T*)p;
}

extern "C" void kernel_launch(void* const* d_in, const int* in_sizes, int n_in,
                              void* d_out, int out_size)
{
    const float* u          = (const float*)d_in[0];
    const float* norm_scale = (const float*)d_in[1];
    const float* norm_bias  = (const float*)d_in[2];
    const float* in_proj_w  = (const float*)d_in[3];
    const float* A_log      = (const float*)d_in[4];
    const float* dt_bias    = (const float*)d_in[5];
    const float* bcB_scale  = (const float*)d_in[6];
    const float* bcC_scale  = (const float*)d_in[7];
    const float* B_bias     = (const float*)d_in[8];
    const float* C_bias     = (const float*)d_in[9];
    const float* theta_w    = (const float*)d_in[10];
    const float* Dv         = (const float*)d_in[11];
    const float* out_proj_w = (const float*)d_in[12];
    float* out = (float*)d_out;

    __nv_bfloat16* p_a3  = sym_addr<__nv_bfloat16>(g_a3);
    __nv_bfloat16* p_yz3 = sym_addr<__nv_bfloat16>(g_yz3);
    __nv_bfloat16* p_w31 = sym_addr<__nv_bfloat16>(g_w31);
    __nv_bfloat16* p_w32 = sym_addr<__nv_bfloat16>(g_w32);

    static bool attr_done = false;
    if (!attr_done) {
        cudaFuncSetAttribute(k_gemm_mma<0>,
            cudaFuncAttributeMaxDynamicSharedMemorySize, GSMEM);
        cudaFuncSetAttribute(k_gemm_mma<1>,
            cudaFuncAttributeMaxDynamicSharedMemorySize, GSMEM);
        cudaFuncSetAttribute(k_scan,
            cudaFuncAttributeMaxDynamicSharedMemorySize, SCAN_SMEM);
        attr_done = true;
    }

    // 1. layernorm + hi/lo pack + theta
    k_ln_theta<<<MROWS, 256>>>(u, norm_scale, norm_bias, theta_w);
    // 2. weight transpose + hi/lo pack
    k_tsplit<<<dim3(NPAD1 / 32, DMODEL / 32), dim3(32, 8)>>>(
        in_proj_w, DMODEL, PROJ, p_w31);
    k_tsplit<<<dim3(DMODEL / 32, DINNER / 32), dim3(32, 8)>>>(
        out_proj_w, DINNER, DMODEL, p_w32);
    // 3. proj GEMM (fused epilogue: silu(x), silu(z), tail)
    k_gemm_mma<0><<<dim3(NPAD1 / 128, MROWS / 128), 256, GSMEM>>>(
        p_a3, p_w31, nullptr, nullptr, PROJ, K3_1);
    // 4. tail prep
    k_prep<<<MROWS, 96>>>(A_log, dt_bias, bcB_scale, bcC_scale, B_bias, C_bias);
    // 5. cumsum(phi) + fused RoPE
    k_cs_chunk<<<BB * 64, 32>>>();
    k_cs_scan<<<1, 128>>>();
    k_cs_add_rope<<<BB * 64, 256>>>();
    // 6. SSD scan + gate + pack (fused, f32x2)
    k_scan<<<256, 256, SCAN_SMEM>>>(Dv);
    // 7. out = yz @ out_proj_w + u
    k_gemm_mma<1><<<dim3(DMODEL / 128, MROWS / 128), 256, GSMEM>>>(
        p_yz3, p_w32, u, out, DMODEL, K3_2);
}